// round 4
// baseline (speedup 1.0000x reference)
#include <cuda_runtime.h>
#include <math.h>

#define NTOK 4096
#define HID  1152
#define NH   16
#define HD   72

// ---- scratch (device globals; allocation-free rule) ----
__device__ __align__(16) float g_raw[3][(size_t)NTOK * HID];      // raw q/k/v projections, n-major
__device__ __align__(16) float g_qkv[3][(size_t)NH * NTOK * HD];  // normed+roped, head-major [h][n][d]
__device__ __align__(16) float g_ao[(size_t)NTOK * HID];          // attention output, n-major

// ================= SGEMM: C[MxN] = A[MxK] * B[KxN], all row-major =================
// 64x64 tile, BK=16, 256 threads, 4x4 per thread.
__global__ void __launch_bounds__(256) sgemm64(
    const float* __restrict__ A, const float* __restrict__ B,
    float* __restrict__ C, int M, int N, int K)
{
    __shared__ float As[16][64];
    __shared__ float Bs[16][64];
    const int t  = threadIdx.x;
    const int tx = t & 15, ty = t >> 4;
    const int bm = blockIdx.y << 6;
    const int bn = blockIdx.x << 6;

    const int am  = t >> 2;         // 0..63 (A row in tile)
    const int ak  = (t & 3) << 2;   // 0,4,8,12 (A k offset)
    const int bk  = t >> 4;         // 0..15 (B k in tile)
    const int bn4 = (t & 15) << 2;  // B n offset

    float acc[4][4] = {};
    for (int k0 = 0; k0 < K; k0 += 16) {
        float4 av = *(const float4*)&A[(size_t)(bm + am) * K + k0 + ak];
        float4 bv = *(const float4*)&B[(size_t)(k0 + bk) * N + bn + bn4];
        __syncthreads();
        As[ak + 0][am] = av.x;
        As[ak + 1][am] = av.y;
        As[ak + 2][am] = av.z;
        As[ak + 3][am] = av.w;
        *(float4*)&Bs[bk][bn4] = bv;
        __syncthreads();
#pragma unroll
        for (int k = 0; k < 16; k++) {
            float4 a = *(const float4*)&As[k][ty << 2];
            float4 b = *(const float4*)&Bs[k][tx << 2];
            acc[0][0] += a.x * b.x; acc[0][1] += a.x * b.y; acc[0][2] += a.x * b.z; acc[0][3] += a.x * b.w;
            acc[1][0] += a.y * b.x; acc[1][1] += a.y * b.y; acc[1][2] += a.y * b.z; acc[1][3] += a.y * b.w;
            acc[2][0] += a.z * b.x; acc[2][1] += a.z * b.y; acc[2][2] += a.z * b.z; acc[2][3] += a.z * b.w;
            acc[3][0] += a.w * b.x; acc[3][1] += a.w * b.y; acc[3][2] += a.w * b.z; acc[3][3] += a.w * b.w;
        }
    }
#pragma unroll
    for (int i = 0; i < 4; i++) {
        float4 r = make_float4(acc[i][0], acc[i][1], acc[i][2], acc[i][3]);
        *(float4*)&C[(size_t)(bm + (ty << 2) + i) * N + bn + (tx << 2)] = r;
    }
}

// ================= RMS-norm + 2D RoPE, writes head-major =================
// One warp per (token, head). blockDim=128 (4 warps). gridDim.y = 3 selects q/k/v.
__global__ void __launch_bounds__(128) normrope_kernel(
    const float* __restrict__ cosb, const float* __restrict__ sinb,
    const float* __restrict__ q_scale, const float* __restrict__ k_scale)
{
    const int z    = blockIdx.y;            // 0=q, 1=k, 2=v
    const int warp = threadIdx.x >> 5;
    const int lane = threadIdx.x & 31;
    const int pair = blockIdx.x * 4 + warp;
    const int n = pair >> 4;
    const int h = pair & 15;

    __shared__ float ybuf[4][HD];

    const float* src = &g_raw[z][(size_t)n * HID + h * HD];
    float x0 = src[lane];
    float x1 = src[lane + 32];
    float x2 = (lane < 8) ? src[lane + 64] : 0.f;

    float ss = x0 * x0 + x1 * x1 + x2 * x2;
#pragma unroll
    for (int o = 16; o > 0; o >>= 1) ss += __shfl_xor_sync(0xffffffffu, ss, o);
    float r = rsqrtf(ss * (1.0f / 72.0f) + 1e-6f);

    float* dst = &g_qkv[z][((size_t)h * NTOK + n) * HD];
    if (z == 2) {
        // v: norm only (no weight), no rope
        dst[lane] = x0 * r;
        dst[lane + 32] = x1 * r;
        if (lane < 8) dst[lane + 64] = x2 * r;
    } else {
        const float* sc = (z == 0) ? q_scale : k_scale;
        ybuf[warp][lane]      = x0 * r * sc[lane];
        ybuf[warp][lane + 32] = x1 * r * sc[lane + 32];
        if (lane < 8) ybuf[warp][lane + 64] = x2 * r * sc[lane + 64];
        __syncwarp();
        const float* cr = &cosb[(size_t)n * HD];
        const float* sr = &sinb[(size_t)n * HD];
        for (int i = lane; i < HD; i += 32) {
            int b = i % 36;
            float y = ybuf[warp][i];
            float c = cr[i], s = sr[i];
            float out;
            if (b < 18) out = y * c - ybuf[warp][i + 18] * s;
            else        out = y * c + ybuf[warp][i - 18] * s;
            dst[i] = out;
        }
    }
}

// ================= Flash attention =================
// One CTA per (64-query block, head). 256 threads as 16x16.
// Q,K staged transposed [d][c] with XOR swizzle on 4-float granules -> conflict-free LDS.128.
#define ATTN_SMEM_FLOATS (72*64 + 72*64 + 64*80 + 64*68)

__global__ void __launch_bounds__(256) attn_kernel(float* __restrict__ outp)
{
    extern __shared__ float sm[];
    float* Qst = sm;                 // [72][64] swizzled (col = query row in tile)
    float* Kst = Qst + 72 * 64;      // [72][64] swizzled (col = key row in tile)
    float* Vs  = Kst + 72 * 64;      // [64][80] row-major
    float* Ps  = Vs  + 64 * 80;      // [64][68]

    const int h  = blockIdx.y;
    const int qb = blockIdx.x << 6;
    const int t  = threadIdx.x;
    const int tx = t & 15, ty = t >> 4;

    const float* Qg = &g_qkv[0][(size_t)h * NTOK * HD];
    const float* Kg = &g_qkv[1][(size_t)h * NTOK * HD];
    const float* Vg = &g_qkv[2][(size_t)h * NTOK * HD];

    // ---- load Q tile, transposed + swizzled ----
    for (int idx = t; idx < 64 * 18; idx += 256) {
        int c = idx / 18, f4 = idx % 18;
        float4 v = *(const float4*)&Qg[(size_t)(qb + c) * HD + (f4 << 2)];
        int g = c >> 2, l = c & 3;
        float vv[4] = {v.x, v.y, v.z, v.w};
#pragma unroll
        for (int j = 0; j < 4; j++) {
            int d = (f4 << 2) + j;
            Qst[d * 64 + ((g ^ (d & 15)) << 2) + l] = vv[j];
        }
    }

    float m_i[4], l_i[4], o[4][5];
#pragma unroll
    for (int i = 0; i < 4; i++) {
        m_i[i] = -1e30f; l_i[i] = 0.f;
#pragma unroll
        for (int dd = 0; dd < 5; dd++) o[i][dd] = 0.f;
    }

    const float4* Q4 = (const float4*)Qst;
    const float4* K4 = (const float4*)Kst;

    for (int kb = 0; kb < NTOK; kb += 64) {
        __syncthreads();  // protect smem from previous iteration's readers
        // ---- load K (transposed+swizzled) and V (row-major, stride 80) ----
        for (int idx = t; idx < 64 * 18; idx += 256) {
            int c = idx / 18, f4 = idx % 18;
            float4 v = *(const float4*)&Kg[(size_t)(kb + c) * HD + (f4 << 2)];
            int g = c >> 2, l = c & 3;
            float vv[4] = {v.x, v.y, v.z, v.w};
#pragma unroll
            for (int j = 0; j < 4; j++) {
                int d = (f4 << 2) + j;
                Kst[d * 64 + ((g ^ (d & 15)) << 2) + l] = vv[j];
            }
            float4 w = *(const float4*)&Vg[(size_t)(kb + c) * HD + (f4 << 2)];
            *(float4*)&Vs[c * 80 + (f4 << 2)] = w;
        }
        __syncthreads();

        // ---- S = Q K^T (64x64 tile, 4x4 per thread) ----
        float s[4][4] = {};
#pragma unroll 8
        for (int d = 0; d < HD; d++) {
            float4 a = Q4[d * 16 + (ty ^ (d & 15))];
            float4 b = K4[d * 16 + (tx ^ (d & 15))];
            s[0][0] += a.x * b.x; s[0][1] += a.x * b.y; s[0][2] += a.x * b.z; s[0][3] += a.x * b.w;
            s[1][0] += a.y * b.x; s[1][1] += a.y * b.y; s[1][2] += a.y * b.z; s[1][3] += a.y * b.w;
            s[2][0] += a.z * b.x; s[2][1] += a.z * b.y; s[2][2] += a.z * b.z; s[2][3] += a.z * b.w;
            s[3][0] += a.w * b.x; s[3][1] += a.w * b.y; s[3][2] += a.w * b.z; s[3][3] += a.w * b.w;
        }

        // ---- online softmax update + stage P to smem ----
#pragma unroll
        for (int i = 0; i < 4; i++) {
            float mt = fmaxf(fmaxf(s[i][0], s[i][1]), fmaxf(s[i][2], s[i][3]));
#pragma unroll
            for (int off = 8; off > 0; off >>= 1)
                mt = fmaxf(mt, __shfl_xor_sync(0xffffffffu, mt, off, 16));
            float mn = fmaxf(m_i[i], mt);
            float alpha = __expf(m_i[i] - mn);
            m_i[i] = mn;
            float p0 = __expf(s[i][0] - mn);
            float p1 = __expf(s[i][1] - mn);
            float p2 = __expf(s[i][2] - mn);
            float p3 = __expf(s[i][3] - mn);
            float rs = p0 + p1 + p2 + p3;
#pragma unroll
            for (int off = 8; off > 0; off >>= 1)
                rs += __shfl_xor_sync(0xffffffffu, rs, off, 16);
            l_i[i] = l_i[i] * alpha + rs;
#pragma unroll
            for (int dd = 0; dd < 5; dd++) o[i][dd] *= alpha;
            *(float4*)&Ps[((ty << 2) + i) * 68 + (tx << 2)] = make_float4(p0, p1, p2, p3);
        }
        __syncthreads();

        // ---- O += P @ V (O cols: tx*5 .. tx*5+4, 72 padded to 80) ----
#pragma unroll 2
        for (int c = 0; c < 64; c++) {
            float p0 = Ps[((ty << 2) + 0) * 68 + c];
            float p1 = Ps[((ty << 2) + 1) * 68 + c];
            float p2 = Ps[((ty << 2) + 2) * 68 + c];
            float p3 = Ps[((ty << 2) + 3) * 68 + c];
            const float* vr = &Vs[c * 80 + tx * 5];
#pragma unroll
            for (int dd = 0; dd < 5; dd++) {
                float v = vr[dd];
                o[0][dd] += p0 * v;
                o[1][dd] += p1 * v;
                o[2][dd] += p2 * v;
                o[3][dd] += p3 * v;
            }
        }
    }

    // ---- normalize and write (n-major, [n][h*72+d]) ----
#pragma unroll
    for (int i = 0; i < 4; i++) {
        float inv = 1.0f / l_i[i];
        int row = qb + (ty << 2) + i;
#pragma unroll
        for (int dd = 0; dd < 5; dd++) {
            int dcol = tx * 5 + dd;
            if (dcol < HD)
                outp[(size_t)row * HID + h * HD + dcol] = o[i][dd] * inv;
        }
    }
}

// ================= launch =================
extern "C" void kernel_launch(void* const* d_in, const int* in_sizes, int n_in,
                              void* d_out, int out_size)
{
    const float* hs   = (const float*)d_in[0];
    const float* cosb = (const float*)d_in[1];
    const float* sinb = (const float*)d_in[2];
    const float* Wq   = (const float*)d_in[3];
    const float* Wk   = (const float*)d_in[4];
    const float* Wv   = (const float*)d_in[5];
    const float* Wo   = (const float*)d_in[6];
    const float* qsc  = (const float*)d_in[7];
    const float* ksc  = (const float*)d_in[8];
    float* out = (float*)d_out;
    (void)in_sizes; (void)n_in; (void)out_size;

    void* p;
    cudaGetSymbolAddress(&p, g_raw);
    float* raw = (float*)p;
    cudaGetSymbolAddress(&p, g_ao);
    float* ao = (float*)p;

    const size_t plane = (size_t)NTOK * HID;
    dim3 gg(HID / 64, NTOK / 64);

    // QKV projections
    sgemm64<<<gg, 256>>>(hs, Wq, raw + 0 * plane, NTOK, HID, HID);
    sgemm64<<<gg, 256>>>(hs, Wk, raw + 1 * plane, NTOK, HID, HID);
    sgemm64<<<gg, 256>>>(hs, Wv, raw + 2 * plane, NTOK, HID, HID);

    // RMS-norm + RoPE, head-major repack
    normrope_kernel<<<dim3(NTOK * NH / 4, 3), 128>>>(cosb, sinb, qsc, ksc);

    // Flash attention
    const int smem_bytes = ATTN_SMEM_FLOATS * (int)sizeof(float);
    cudaFuncSetAttribute(attn_kernel, cudaFuncAttributeMaxDynamicSharedMemorySize, smem_bytes);
    attn_kernel<<<dim3(NTOK / 64, NH), 256, smem_bytes>>>(ao);

    // Output projection
    sgemm64<<<gg, 256>>>(ao, Wo, out, NTOK, HID, HID);
}

// round 15
// speedup vs baseline: 1.2790x; 1.2790x over previous
#include <cuda_runtime.h>
#include <cuda_bf16.h>
#include <math.h>
#include <stdint.h>

#define NTOK 4096
#define HID  1152
#define NH   16
#define HD   72

// ---- scratch (device globals; allocation-free rule) ----
__device__ __align__(16) float g_raw[3][(size_t)NTOK * HID];      // raw q/k/v projections
__device__ __align__(16) float g_qkv[3][(size_t)NH * NTOK * HD];  // normed+roped, head-major
__device__ __align__(16) float g_ao[(size_t)NTOK * HID];          // attention output
__device__ __align__(16) __nv_bfloat16 g_ahi[(size_t)NTOK * HID]; // split activations
__device__ __align__(16) __nv_bfloat16 g_alo[(size_t)NTOK * HID];
__device__ __align__(16) __nv_bfloat16 g_wt[4][2][(size_t)HID * HID]; // [mat][hi/lo], [N][K] transposed

// ================= helpers =================
__device__ __forceinline__ uint32_t smem_u32(const void* p) {
    uint32_t a;
    asm("{ .reg .u64 t; cvta.to.shared.u64 t, %1; cvt.u32.u64 %0, t; }" : "=r"(a) : "l"(p));
    return a;
}

// portable tensor-core ops (sm_80+ PTX -> HMMA on sm_103)
#define LDSM4(r, a) \
    asm volatile("ldmatrix.sync.aligned.m8n8.x4.shared.b16 {%0,%1,%2,%3}, [%4];" \
        : "=r"((r)[0]), "=r"((r)[1]), "=r"((r)[2]), "=r"((r)[3]) : "r"(a))
#define LDSM2(r, a) \
    asm volatile("ldmatrix.sync.aligned.m8n8.x2.shared.b16 {%0,%1}, [%2];" \
        : "=r"((r)[0]), "=r"((r)[1]) : "r"(a))
#define MMA16816(c, a, b) \
    asm volatile("mma.sync.aligned.m16n8k16.row.col.f32.bf16.bf16.f32 " \
        "{%0,%1,%2,%3}, {%4,%5,%6,%7}, {%8,%9}, {%0,%1,%2,%3};" \
        : "+f"((c)[0]), "+f"((c)[1]), "+f"((c)[2]), "+f"((c)[3]) \
        : "r"((a)[0]), "r"((a)[1]), "r"((a)[2]), "r"((a)[3]), "r"((b)[0]), "r"((b)[1]))

// XOR swizzle of 16B granules within 128B rows (conflict-free ldmatrix)
#define SWZ(o) ((o) ^ ((((uint32_t)(o)) >> 3) & 0x70u))

// ================= weight transpose + bf16 hi/lo split =================
// W: [K=1152][N=1152] row-major -> wt_hi/lo: [N][K]
__global__ void __launch_bounds__(256) transpose_split(
    const float* __restrict__ W, __nv_bfloat16* __restrict__ hi, __nv_bfloat16* __restrict__ lo)
{
    __shared__ float tile[32][33];
    const int tx = threadIdx.x, ty = threadIdx.y;
    const int bx = blockIdx.x * 32, by = blockIdx.y * 32;
#pragma unroll
    for (int j = 0; j < 32; j += 8)
        tile[ty + j][tx] = W[(size_t)(by + ty + j) * HID + bx + tx];
    __syncthreads();
#pragma unroll
    for (int j = 0; j < 32; j += 8) {
        float v = tile[tx][ty + j];                    // = W[by+tx][bx+ty+j]
        __nv_bfloat16 h = __float2bfloat16(v);
        __nv_bfloat16 l = __float2bfloat16(v - __bfloat162float(h));
        size_t o = (size_t)(bx + ty + j) * HID + by + tx;
        hi[o] = h; lo[o] = l;
    }
}

// ================= activation bf16 hi/lo split =================
__global__ void __launch_bounds__(256) split_act(
    const float* __restrict__ x, __nv_bfloat16* __restrict__ hi, __nv_bfloat16* __restrict__ lo)
{
    size_t i = ((size_t)blockIdx.x * 256 + threadIdx.x) * 4;
    float4 v = *(const float4*)&x[i];
    __nv_bfloat16 h0 = __float2bfloat16(v.x), h1 = __float2bfloat16(v.y);
    __nv_bfloat16 h2 = __float2bfloat16(v.z), h3 = __float2bfloat16(v.w);
    __nv_bfloat162 H01; H01.x = h0; H01.y = h1;
    __nv_bfloat162 H23; H23.x = h2; H23.y = h3;
    __nv_bfloat162 L01, L23;
    L01.x = __float2bfloat16(v.x - __bfloat162float(h0));
    L01.y = __float2bfloat16(v.y - __bfloat162float(h1));
    L23.x = __float2bfloat16(v.z - __bfloat162float(h2));
    L23.y = __float2bfloat16(v.w - __bfloat162float(h3));
    *(__nv_bfloat162*)&hi[i]     = H01;
    *(__nv_bfloat162*)&hi[i + 2] = H23;
    *(__nv_bfloat162*)&lo[i]     = L01;
    *(__nv_bfloat162*)&lo[i + 2] = L23;
}

// ================= mma.sync bf16 split-compensated GEMM =================
// C[M,N] = A[M,K] * B[N,K]^T. 128x128 CTA tile, 8 warps (4m x 2n), warp = 32m x 64n.
// KC=64 chunk: 128 rows x 128B, XOR-swizzled 16B granules.
#define KC 64
#define GEMM_SMEM_BYTES 65536

__global__ void __launch_bounds__(256) gemm_bf16c(
    const __nv_bfloat16* __restrict__ Ahi, const __nv_bfloat16* __restrict__ Alo,
    const __nv_bfloat16* __restrict__ Bhi, const __nv_bfloat16* __restrict__ Blo,
    float* __restrict__ C, int M, int N, int K)
{
    extern __shared__ char smd[];
    const uint32_t smb = smem_u32(smd);
    const uint32_t SA_HI = 0, SA_LO = 16384, SB_HI = 32768, SB_LO = 49152;

    const int t = threadIdx.x, lane = t & 31, wid = t >> 5;
    const int wm = wid >> 1, wn = wid & 1;
    const int m0 = blockIdx.y << 7, n0 = blockIdx.x << 7;

    float c[2][8][4];
#pragma unroll
    for (int mt = 0; mt < 2; mt++)
#pragma unroll
        for (int nt = 0; nt < 8; nt++)
#pragma unroll
            for (int q = 0; q < 4; q++) c[mt][nt][q] = 0.f;

    // per-lane ldmatrix row patterns
    const int amat = lane >> 3;                          // 0..3
    const int arow = (lane & 7) + ((amat & 1) << 3);     // row within 16-row tile
    const int agp  = amat >> 1;                          // k-granule parity
    const int brow = lane & 7;                           // row within 8-row tile
    const int bgp  = (lane >> 3) & 1;

    for (int kc = 0; kc < K; kc += KC) {
        __syncthreads();
        // stage chunk: 4 buffers x 128 rows x 8 granules of 16B
        for (int s = t; s < 1024; s += 256) {
            int r = s >> 3, sub = s & 7;
            uint32_t sw = SWZ((uint32_t)(r * 128 + sub * 16));
            size_t ga = (size_t)(m0 + r) * K + kc + sub * 8;
            size_t gb = (size_t)(n0 + r) * K + kc + sub * 8;
            *(float4*)(smd + SA_HI + sw) = *(const float4*)&Ahi[ga];
            *(float4*)(smd + SA_LO + sw) = *(const float4*)&Alo[ga];
            *(float4*)(smd + SB_HI + sw) = *(const float4*)&Bhi[gb];
            *(float4*)(smd + SB_LO + sw) = *(const float4*)&Blo[gb];
        }
        __syncthreads();

#pragma unroll
        for (int ks = 0; ks < 4; ks++) {
            uint32_t ahi[2][4], alo[2][4];
#pragma unroll
            for (int mt = 0; mt < 2; mt++) {
                int row = wm * 32 + mt * 16 + arow;
                uint32_t off = (uint32_t)(row * 128 + (((ks * 2 + agp) ^ (row & 7)) << 4));
                LDSM4(ahi[mt], smb + SA_HI + off);
                LDSM4(alo[mt], smb + SA_LO + off);
            }
#pragma unroll
            for (int nt = 0; nt < 8; nt++) {
                int row = wn * 64 + nt * 8 + brow;
                uint32_t off = (uint32_t)(row * 128 + (((ks * 2 + bgp) ^ (row & 7)) << 4));
                uint32_t bh[2], bl[2];
                LDSM2(bh, smb + SB_HI + off);
                LDSM2(bl, smb + SB_LO + off);
#pragma unroll
                for (int mt = 0; mt < 2; mt++) {
                    MMA16816(c[mt][nt], ahi[mt], bh);
                    MMA16816(c[mt][nt], ahi[mt], bl);
                    MMA16816(c[mt][nt], alo[mt], bh);
                }
            }
        }
    }

    // epilogue: fragment mapping m = l>>2 (+8), n = (l&3)*2
    const int mw = m0 + wm * 32, nw = n0 + wn * 64;
#pragma unroll
    for (int mt = 0; mt < 2; mt++)
#pragma unroll
        for (int nt = 0; nt < 8; nt++) {
            int m = mw + mt * 16 + (lane >> 2);
            int n = nw + nt * 8 + (lane & 3) * 2;
            *(float2*)&C[(size_t)m * N + n]       = make_float2(c[mt][nt][0], c[mt][nt][1]);
            *(float2*)&C[(size_t)(m + 8) * N + n] = make_float2(c[mt][nt][2], c[mt][nt][3]);
        }
}

// ================= RMS-norm + 2D RoPE (unchanged) =================
__global__ void __launch_bounds__(128) normrope_kernel(
    const float* __restrict__ cosb, const float* __restrict__ sinb,
    const float* __restrict__ q_scale, const float* __restrict__ k_scale)
{
    const int z    = blockIdx.y;
    const int warp = threadIdx.x >> 5;
    const int lane = threadIdx.x & 31;
    const int pair = blockIdx.x * 4 + warp;
    const int n = pair >> 4;
    const int h = pair & 15;

    __shared__ float ybuf[4][HD];

    const float* src = &g_raw[z][(size_t)n * HID + h * HD];
    float x0 = src[lane];
    float x1 = src[lane + 32];
    float x2 = (lane < 8) ? src[lane + 64] : 0.f;

    float ss = x0 * x0 + x1 * x1 + x2 * x2;
#pragma unroll
    for (int o = 16; o > 0; o >>= 1) ss += __shfl_xor_sync(0xffffffffu, ss, o);
    float r = rsqrtf(ss * (1.0f / 72.0f) + 1e-6f);

    float* dst = &g_qkv[z][((size_t)h * NTOK + n) * HD];
    if (z == 2) {
        dst[lane] = x0 * r;
        dst[lane + 32] = x1 * r;
        if (lane < 8) dst[lane + 64] = x2 * r;
    } else {
        const float* sc = (z == 0) ? q_scale : k_scale;
        ybuf[warp][lane]      = x0 * r * sc[lane];
        ybuf[warp][lane + 32] = x1 * r * sc[lane + 32];
        if (lane < 8) ybuf[warp][lane + 64] = x2 * r * sc[lane + 64];
        __syncwarp();
        const float* cr = &cosb[(size_t)n * HD];
        const float* sr = &sinb[(size_t)n * HD];
        for (int i = lane; i < HD; i += 32) {
            int b = i % 36;
            float y = ybuf[warp][i];
            float c = cr[i], s = sr[i];
            float out;
            if (b < 18) out = y * c - ybuf[warp][i + 18] * s;
            else        out = y * c + ybuf[warp][i - 18] * s;
            dst[i] = out;
        }
    }
}

// ================= Flash attention (unchanged) =================
#define ATTN_SMEM_FLOATS (72*64 + 72*64 + 64*80 + 64*68)

__global__ void __launch_bounds__(256) attn_kernel(float* __restrict__ outp)
{
    extern __shared__ float smf[];
    float* Qst = smf;
    float* Kst = Qst + 72 * 64;
    float* Vs  = Kst + 72 * 64;
    float* Ps  = Vs  + 64 * 80;

    const int h  = blockIdx.y;
    const int qb = blockIdx.x << 6;
    const int t  = threadIdx.x;
    const int tx = t & 15, ty = t >> 4;

    const float* Qg = &g_qkv[0][(size_t)h * NTOK * HD];
    const float* Kg = &g_qkv[1][(size_t)h * NTOK * HD];
    const float* Vg = &g_qkv[2][(size_t)h * NTOK * HD];

    for (int idx = t; idx < 64 * 18; idx += 256) {
        int c = idx / 18, f4 = idx % 18;
        float4 v = *(const float4*)&Qg[(size_t)(qb + c) * HD + (f4 << 2)];
        int g = c >> 2, l = c & 3;
        float vv[4] = {v.x, v.y, v.z, v.w};
#pragma unroll
        for (int j = 0; j < 4; j++) {
            int d = (f4 << 2) + j;
            Qst[d * 64 + ((g ^ (d & 15)) << 2) + l] = vv[j];
        }
    }

    float m_i[4], l_i[4], o[4][5];
#pragma unroll
    for (int i = 0; i < 4; i++) {
        m_i[i] = -1e30f; l_i[i] = 0.f;
#pragma unroll
        for (int dd = 0; dd < 5; dd++) o[i][dd] = 0.f;
    }

    const float4* Q4 = (const float4*)Qst;
    const float4* K4 = (const float4*)Kst;

    for (int kb = 0; kb < NTOK; kb += 64) {
        __syncthreads();
        for (int idx = t; idx < 64 * 18; idx += 256) {
            int c = idx / 18, f4 = idx % 18;
            float4 v = *(const float4*)&Kg[(size_t)(kb + c) * HD + (f4 << 2)];
            int g = c >> 2, l = c & 3;
            float vv[4] = {v.x, v.y, v.z, v.w};
#pragma unroll
            for (int j = 0; j < 4; j++) {
                int d = (f4 << 2) + j;
                Kst[d * 64 + ((g ^ (d & 15)) << 2) + l] = vv[j];
            }
            float4 w = *(const float4*)&Vg[(size_t)(kb + c) * HD + (f4 << 2)];
            *(float4*)&Vs[c * 80 + (f4 << 2)] = w;
        }
        __syncthreads();

        float s[4][4] = {};
#pragma unroll 8
        for (int d = 0; d < HD; d++) {
            float4 a = Q4[d * 16 + (ty ^ (d & 15))];
            float4 b = K4[d * 16 + (tx ^ (d & 15))];
            s[0][0] += a.x * b.x; s[0][1] += a.x * b.y; s[0][2] += a.x * b.z; s[0][3] += a.x * b.w;
            s[1][0] += a.y * b.x; s[1][1] += a.y * b.y; s[1][2] += a.y * b.z; s[1][3] += a.y * b.w;
            s[2][0] += a.z * b.x; s[2][1] += a.z * b.y; s[2][2] += a.z * b.z; s[2][3] += a.z * b.w;
            s[3][0] += a.w * b.x; s[3][1] += a.w * b.y; s[3][2] += a.w * b.z; s[3][3] += a.w * b.w;
        }

#pragma unroll
        for (int i = 0; i < 4; i++) {
            float mt = fmaxf(fmaxf(s[i][0], s[i][1]), fmaxf(s[i][2], s[i][3]));
#pragma unroll
            for (int off = 8; off > 0; off >>= 1)
                mt = fmaxf(mt, __shfl_xor_sync(0xffffffffu, mt, off, 16));
            float mn = fmaxf(m_i[i], mt);
            float alpha = __expf(m_i[i] - mn);
            m_i[i] = mn;
            float p0 = __expf(s[i][0] - mn);
            float p1 = __expf(s[i][1] - mn);
            float p2 = __expf(s[i][2] - mn);
            float p3 = __expf(s[i][3] - mn);
            float rs = p0 + p1 + p2 + p3;
#pragma unroll
            for (int off = 8; off > 0; off >>= 1)
                rs += __shfl_xor_sync(0xffffffffu, rs, off, 16);
            l_i[i] = l_i[i] * alpha + rs;
#pragma unroll
            for (int dd = 0; dd < 5; dd++) o[i][dd] *= alpha;
            *(float4*)&Ps[((ty << 2) + i) * 68 + (tx << 2)] = make_float4(p0, p1, p2, p3);
        }
        __syncthreads();

#pragma unroll 2
        for (int c = 0; c < 64; c++) {
            float p0 = Ps[((ty << 2) + 0) * 68 + c];
            float p1 = Ps[((ty << 2) + 1) * 68 + c];
            float p2 = Ps[((ty << 2) + 2) * 68 + c];
            float p3 = Ps[((ty << 2) + 3) * 68 + c];
            const float* vr = &Vs[c * 80 + tx * 5];
#pragma unroll
            for (int dd = 0; dd < 5; dd++) {
                float v = vr[dd];
                o[0][dd] += p0 * v;
                o[1][dd] += p1 * v;
                o[2][dd] += p2 * v;
                o[3][dd] += p3 * v;
            }
        }
    }

#pragma unroll
    for (int i = 0; i < 4; i++) {
        float inv = 1.0f / l_i[i];
        int row = qb + (ty << 2) + i;
#pragma unroll
        for (int dd = 0; dd < 5; dd++) {
            int dcol = tx * 5 + dd;
            if (dcol < HD)
                outp[(size_t)row * HID + h * HD + dcol] = o[i][dd] * inv;
        }
    }
}

// ================= launch =================
extern "C" void kernel_launch(void* const* d_in, const int* in_sizes, int n_in,
                              void* d_out, int out_size)
{
    const float* hs   = (const float*)d_in[0];
    const float* cosb = (const float*)d_in[1];
    const float* sinb = (const float*)d_in[2];
    const float* Wq   = (const float*)d_in[3];
    const float* Wk   = (const float*)d_in[4];
    const float* Wv   = (const float*)d_in[5];
    const float* Wo   = (const float*)d_in[6];
    const float* qsc  = (const float*)d_in[7];
    const float* ksc  = (const float*)d_in[8];
    float* out = (float*)d_out;
    (void)in_sizes; (void)n_in; (void)out_size;

    void* p;
    cudaGetSymbolAddress(&p, g_raw); float* raw = (float*)p;
    cudaGetSymbolAddress(&p, g_ao);  float* ao  = (float*)p;
    cudaGetSymbolAddress(&p, g_ahi); __nv_bfloat16* ahi = (__nv_bfloat16*)p;
    cudaGetSymbolAddress(&p, g_alo); __nv_bfloat16* alo = (__nv_bfloat16*)p;
    cudaGetSymbolAddress(&p, g_wt);  __nv_bfloat16* wt  = (__nv_bfloat16*)p;
    const size_t wplane = (size_t)HID * HID;
    const size_t plane  = (size_t)NTOK * HID;

    // one-time attrs (idempotent)
    cudaFuncSetAttribute(gemm_bf16c, cudaFuncAttributeMaxDynamicSharedMemorySize, GEMM_SMEM_BYTES);
    cudaFuncSetAttribute(attn_kernel, cudaFuncAttributeMaxDynamicSharedMemorySize,
                         ATTN_SMEM_FLOATS * (int)sizeof(float));

    // weight transpose+split: wt[m][0/1] = hi/lo of W_m^T  ([N][K])
    dim3 tb(32, 8), tg(HID / 32, HID / 32);
    transpose_split<<<tg, tb>>>(Wq, wt + (0 * 2 + 0) * wplane, wt + (0 * 2 + 1) * wplane);
    transpose_split<<<tg, tb>>>(Wk, wt + (1 * 2 + 0) * wplane, wt + (1 * 2 + 1) * wplane);
    transpose_split<<<tg, tb>>>(Wv, wt + (2 * 2 + 0) * wplane, wt + (2 * 2 + 1) * wplane);
    transpose_split<<<tg, tb>>>(Wo, wt + (3 * 2 + 0) * wplane, wt + (3 * 2 + 1) * wplane);

    // split activations (hidden_states)
    split_act<<<(int)(plane / (256 * 4)), 256>>>(hs, ahi, alo);

    // QKV projections on tensor cores
    dim3 gg(HID / 128, NTOK / 128);
    gemm_bf16c<<<gg, 256, GEMM_SMEM_BYTES>>>(ahi, alo, wt + 0 * wplane, wt + 1 * wplane,
                                             raw + 0 * plane, NTOK, HID, HID);
    gemm_bf16c<<<gg, 256, GEMM_SMEM_BYTES>>>(ahi, alo, wt + 2 * wplane, wt + 3 * wplane,
                                             raw + 1 * plane, NTOK, HID, HID);
    gemm_bf16c<<<gg, 256, GEMM_SMEM_BYTES>>>(ahi, alo, wt + 4 * wplane, wt + 5 * wplane,
                                             raw + 2 * plane, NTOK, HID, HID);

    // RMS-norm + RoPE, head-major repack
    normrope_kernel<<<dim3(NTOK * NH / 4, 3), 128>>>(cosb, sinb, qsc, ksc);

    // Flash attention
    attn_kernel<<<dim3(NTOK / 64, NH), 256, ATTN_SMEM_FLOATS * (int)sizeof(float)>>>(ao);

    // output projection on tensor cores
    split_act<<<(int)(plane / (256 * 4)), 256>>>(ao, ahi, alo);
    gemm_bf16c<<<gg, 256, GEMM_SMEM_BYTES>>>(ahi, alo, wt + 6 * wplane, wt + 7 * wplane,
                                             out, NTOK, HID, HID);
}